// round 1
// baseline (speedup 1.0000x reference)
#include <cuda_runtime.h>
#include <math_constants.h>

#define N_NODES 50000
#define N_EDGES 800000
#define M_TOT   850000   // edges + self loops
#define D 128

typedef unsigned long long u64;

// ---------------- scratch (device globals; no allocation allowed) ----------
__device__ float  g_sum[1];
__device__ int    g_deg[N_NODES + 1];
__device__ int    g_rowptr[N_NODES + 1];
__device__ int    g_cnt[N_NODES];
__device__ int    g_csr_src[M_TOT];
__device__ float  g_csr_w[M_TOT];
__device__ float4 g_x0[N_NODES * 32];
__device__ float4 g_xl[N_NODES * 32];
__device__ float4 g_xr[N_NODES * 32];
__device__ float4 g_x1[N_NODES * 32];

// ---------------- f32x2 helpers (FFMA2: PTX-only on sm_103a) ---------------
__device__ __forceinline__ u64 pk2(float a, float b) {
    u64 r; asm("mov.b64 %0,{%1,%2};" : "=l"(r) : "f"(a), "f"(b)); return r;
}
__device__ __forceinline__ void upk2(u64 v, float& a, float& b) {
    asm("mov.b64 {%0,%1},%2;" : "=f"(a), "=f"(b) : "l"(v));
}
__device__ __forceinline__ u64 ffma2(u64 a, u64 b, u64 c) {
    u64 d; asm("fma.rn.f32x2 %0,%1,%2,%3;" : "=l"(d) : "l"(a), "l"(b), "l"(c)); return d;
}

// ---------------- setup kernels --------------------------------------------
__global__ void init_kernel() {
    int i = blockIdx.x * blockDim.x + threadIdx.x;
    if (i <= N_NODES) g_deg[i] = (i < N_NODES) ? 1 : 0;   // +1 = self loop
    if (i == 0) g_sum[0] = 0.f;
}

__global__ void sumw_kernel(const float* __restrict__ ew) {
    int i = blockIdx.x * blockDim.x + threadIdx.x;
    float v = (i < N_EDGES) ? ew[i] : 0.f;
    #pragma unroll
    for (int o = 16; o; o >>= 1) v += __shfl_xor_sync(0xffffffffu, v, o);
    if ((threadIdx.x & 31) == 0) atomicAdd(g_sum, v);
}

__global__ void hist_kernel(const int* __restrict__ ei) {
    int i = blockIdx.x * blockDim.x + threadIdx.x;
    if (i < N_EDGES) atomicAdd(&g_deg[ei[N_EDGES + i]], 1);
}

// single-block exclusive scan over g_deg -> g_rowptr (and copy to g_cnt)
__global__ void scan_kernel() {
    __shared__ int warp_sums[32];
    __shared__ int s_carry;
    int tid = threadIdx.x, lane = tid & 31, wid = tid >> 5;
    if (tid == 0) s_carry = 0;
    __syncthreads();
    for (int base = 0; base < N_NODES; base += 1024) {
        int i = base + tid;
        int v = (i < N_NODES) ? g_deg[i] : 0;
        int x = v;
        #pragma unroll
        for (int o = 1; o < 32; o <<= 1) {
            int y = __shfl_up_sync(0xffffffffu, x, o);
            if (lane >= o) x += y;
        }
        if (lane == 31) warp_sums[wid] = x;
        __syncthreads();
        if (wid == 0) {
            int w = warp_sums[lane];
            #pragma unroll
            for (int o = 1; o < 32; o <<= 1) {
                int y = __shfl_up_sync(0xffffffffu, w, o);
                if (lane >= o) w += y;
            }
            warp_sums[lane] = w;
        }
        __syncthreads();
        int woff = (wid > 0) ? warp_sums[wid - 1] : 0;
        int incl = x + woff;
        int excl = incl - v;
        int carry = s_carry;
        if (i < N_NODES) { g_rowptr[i] = carry + excl; g_cnt[i] = carry + excl; }
        __syncthreads();
        if (tid == 1023) s_carry = carry + incl;
        __syncthreads();
    }
    if (threadIdx.x == 0) g_rowptr[N_NODES] = s_carry;
}

__global__ void scatter_kernel(const int* __restrict__ ei, const float* __restrict__ ew) {
    int i = blockIdx.x * blockDim.x + threadIdx.x;
    if (i >= M_TOT) return;
    int s, d; float w;
    if (i < N_EDGES) { s = ei[i]; d = ei[N_EDGES + i]; w = ew[i]; }
    else             { s = d = i - N_EDGES; w = g_sum[0] * (1.0f / N_EDGES); }
    int pos = atomicAdd(&g_cnt[d], 1);
    g_csr_src[pos] = s;
    g_csr_w[pos]   = w;
}

__global__ void gather_kernel(const int* __restrict__ node_ids, const float* __restrict__ emb) {
    int i = blockIdx.x * blockDim.x + threadIdx.x;
    if (i >= N_NODES * 32) return;
    int node = i >> 5, c = i & 31;
    g_x0[i] = ((const float4*)emb)[node_ids[node] * 32 + c];
}

// ---------------- GEMM: Y[M,128] = X[M,128] @ W[128,128] + B ---------------
// block = (32,8): 64 rows x 128 cols per block. Per thread: 4 row-pairs x 4 cols.
// x staged in smem as (row_even,row_odd) float2 so FFMA2 x-operands come
// straight from LDS.128; W columns pair naturally from LDG.128.
__global__ __launch_bounds__(256) void gemm_kernel(
    const float* __restrict__ X, const float* __restrict__ W,
    const float* __restrict__ B, float* __restrict__ Y)
{
    __shared__ float2 xs[32 * 128];           // [row_pair][k]
    const int tx = threadIdx.x, ty = threadIdx.y;
    const int t  = ty * 32 + tx;
    const int r0 = blockIdx.x * 64;

    #pragma unroll
    for (int i = 0; i < 4; i++) {
        int u  = t + 256 * i;                 // 0..1023
        int rp = u >> 5, c4 = u & 31;
        int ra = r0 + 2 * rp, rb = ra + 1;
        float4 a = (ra < N_NODES) ? *(const float4*)(X + ra * D + c4 * 4) : make_float4(0,0,0,0);
        float4 b = (rb < N_NODES) ? *(const float4*)(X + rb * D + c4 * 4) : make_float4(0,0,0,0);
        xs[rp * 128 + 4 * c4 + 0] = make_float2(a.x, b.x);
        xs[rp * 128 + 4 * c4 + 1] = make_float2(a.y, b.y);
        xs[rp * 128 + 4 * c4 + 2] = make_float2(a.z, b.z);
        xs[rp * 128 + 4 * c4 + 3] = make_float2(a.w, b.w);
    }
    __syncthreads();

    u64 acc[4][4];
    #pragma unroll
    for (int j = 0; j < 4; j++)
        #pragma unroll
        for (int c = 0; c < 4; c++) acc[j][c] = 0ull;

    const float4* W4 = (const float4*)W;
    #pragma unroll 4
    for (int k = 0; k < D; k += 2) {
        float4 wA = W4[k * 32 + tx];
        float4 wB = W4[(k + 1) * 32 + tx];
        u64 wA0 = pk2(wA.x, wA.x), wA1 = pk2(wA.y, wA.y);
        u64 wA2 = pk2(wA.z, wA.z), wA3 = pk2(wA.w, wA.w);
        u64 wB0 = pk2(wB.x, wB.x), wB1 = pk2(wB.y, wB.y);
        u64 wB2 = pk2(wB.z, wB.z), wB3 = pk2(wB.w, wB.w);
        #pragma unroll
        for (int j = 0; j < 4; j++) {
            float4 xv = *(const float4*)&xs[(ty * 4 + j) * 128 + k];
            u64 x0 = pk2(xv.x, xv.y);   // (row_e, row_o) at k
            u64 x1 = pk2(xv.z, xv.w);   // (row_e, row_o) at k+1
            acc[j][0] = ffma2(x0, wA0, acc[j][0]);
            acc[j][1] = ffma2(x0, wA1, acc[j][1]);
            acc[j][2] = ffma2(x0, wA2, acc[j][2]);
            acc[j][3] = ffma2(x0, wA3, acc[j][3]);
            acc[j][0] = ffma2(x1, wB0, acc[j][0]);
            acc[j][1] = ffma2(x1, wB1, acc[j][1]);
            acc[j][2] = ffma2(x1, wB2, acc[j][2]);
            acc[j][3] = ffma2(x1, wB3, acc[j][3]);
        }
    }

    float4 b4 = *(const float4*)(B + tx * 4);
    #pragma unroll
    for (int j = 0; j < 4; j++) {
        int rp = ty * 4 + j;
        int ra = r0 + 2 * rp, rb = ra + 1;
        float e0,o0,e1,o1,e2,o2,e3,o3;
        upk2(acc[j][0], e0, o0); upk2(acc[j][1], e1, o1);
        upk2(acc[j][2], e2, o2); upk2(acc[j][3], e3, o3);
        if (ra < N_NODES)
            *(float4*)(Y + ra * D + tx * 4) = make_float4(e0 + b4.x, e1 + b4.y, e2 + b4.z, e3 + b4.w);
        if (rb < N_NODES)
            *(float4*)(Y + rb * D + tx * 4) = make_float4(o0 + b4.x, o1 + b4.y, o2 + b4.z, o3 + b4.w);
    }
}

// ---------------- fused attention + aggregate + residual + LN --------------
// one warp per dst node; single pass over its CSR edges with online softmax.
__global__ __launch_bounds__(256) void attn_kernel(
    const float* __restrict__ xl, const float* __restrict__ xr,
    const float* __restrict__ We, const float* __restrict__ att,
    const float* __restrict__ bias, const float* __restrict__ gam,
    const float* __restrict__ bet, const float* __restrict__ resid,
    float* __restrict__ out)
{
    int gw   = (blockIdx.x * blockDim.x + threadIdx.x) >> 5;
    int lane = threadIdx.x & 31;
    if (gw >= N_NODES) return;
    int c = lane * 4;

    float4 xr4 = *(const float4*)(xr + gw * D + c);
    float4 We4 = *(const float4*)(We + c);
    float4 at4 = *(const float4*)(att + c);

    int beg = g_rowptr[gw], end = g_rowptr[gw + 1];
    float m = -CUDART_INF_F, s = 0.f;
    float ax = 0.f, ay = 0.f, az = 0.f, aw = 0.f;

    for (int i = beg; i < end; i++) {
        int   sn = g_csr_src[i];
        float w  = g_csr_w[i];
        float4 xv = *(const float4*)(xl + sn * D + c);
        float t0 = xv.x + xr4.x + w * We4.x; t0 = fmaxf(t0, 0.2f * t0);
        float t1 = xv.y + xr4.y + w * We4.y; t1 = fmaxf(t1, 0.2f * t1);
        float t2 = xv.z + xr4.z + w * We4.z; t2 = fmaxf(t2, 0.2f * t2);
        float t3 = xv.w + xr4.w + w * We4.w; t3 = fmaxf(t3, 0.2f * t3);
        float l = t0 * at4.x + t1 * at4.y + t2 * at4.z + t3 * at4.w;
        l += __shfl_xor_sync(0xffffffffu, l, 16);
        l += __shfl_xor_sync(0xffffffffu, l, 8);
        l += __shfl_xor_sync(0xffffffffu, l, 4);
        l += __shfl_xor_sync(0xffffffffu, l, 2);
        l += __shfl_xor_sync(0xffffffffu, l, 1);
        float nm = fmaxf(m, l);
        float cs = __expf(m - nm);   // 0 on first iter (m = -inf)
        float e  = __expf(l - nm);
        s  = s  * cs + e;
        ax = ax * cs + e * xv.x;
        ay = ay * cs + e * xv.y;
        az = az * cs + e * xv.z;
        aw = aw * cs + e * xv.w;
        m = nm;
    }

    float inv = 1.0f / s;
    float4 b4 = *(const float4*)(bias + c);
    float4 r4 = *(const float4*)(resid + gw * D + c);
    float hx = r4.x + ax * inv + b4.x;
    float hy = r4.y + ay * inv + b4.y;
    float hz = r4.z + az * inv + b4.z;
    float hw = r4.w + aw * inv + b4.w;

    float ps = hx + hy + hz + hw;
    ps += __shfl_xor_sync(0xffffffffu, ps, 16);
    ps += __shfl_xor_sync(0xffffffffu, ps, 8);
    ps += __shfl_xor_sync(0xffffffffu, ps, 4);
    ps += __shfl_xor_sync(0xffffffffu, ps, 2);
    ps += __shfl_xor_sync(0xffffffffu, ps, 1);
    float mu = ps * (1.0f / D);

    float dx = hx - mu, dy = hy - mu, dz = hz - mu, dw = hw - mu;
    float q = dx * dx + dy * dy + dz * dz + dw * dw;
    q += __shfl_xor_sync(0xffffffffu, q, 16);
    q += __shfl_xor_sync(0xffffffffu, q, 8);
    q += __shfl_xor_sync(0xffffffffu, q, 4);
    q += __shfl_xor_sync(0xffffffffu, q, 2);
    q += __shfl_xor_sync(0xffffffffu, q, 1);
    float var = q * (1.0f / D);
    float sc  = rsqrtf(var + 1e-5f);

    float4 g4  = *(const float4*)(gam + c);
    float4 be4 = *(const float4*)(bet + c);
    float4 o;
    o.x = dx * sc * g4.x + be4.x;
    o.y = dy * sc * g4.y + be4.y;
    o.z = dz * sc * g4.z + be4.z;
    o.w = dw * sc * g4.w + be4.w;
    *(float4*)(out + gw * D + c) = o;
}

// ---------------- host -----------------------------------------------------
extern "C" void kernel_launch(void* const* d_in, const int* in_sizes, int n_in,
                              void* d_out, int out_size)
{
    const int*   node_ids = (const int*)d_in[0];
    const int*   ei       = (const int*)d_in[1];
    const float* ew       = (const float*)d_in[2];
    const float* emb      = (const float*)d_in[3];
    const float* w1l = (const float*)d_in[4];
    const float* b1l = (const float*)d_in[5];
    const float* w1r = (const float*)d_in[6];
    const float* b1r = (const float*)d_in[7];
    const float* w1e = (const float*)d_in[8];
    const float* at1 = (const float*)d_in[9];
    const float* bi1 = (const float*)d_in[10];
    const float* g1  = (const float*)d_in[11];
    const float* be1 = (const float*)d_in[12];
    const float* w2l = (const float*)d_in[13];
    const float* b2l = (const float*)d_in[14];
    const float* w2r = (const float*)d_in[15];
    const float* b2r = (const float*)d_in[16];
    const float* w2e = (const float*)d_in[17];
    const float* at2 = (const float*)d_in[18];
    const float* bi2 = (const float*)d_in[19];
    const float* g2  = (const float*)d_in[20];
    const float* be2 = (const float*)d_in[21];
    float* out = (float*)d_out;

    float *x0, *xl, *xr, *x1;
    cudaGetSymbolAddress((void**)&x0, g_x0);
    cudaGetSymbolAddress((void**)&xl, g_xl);
    cudaGetSymbolAddress((void**)&xr, g_xr);
    cudaGetSymbolAddress((void**)&x1, g_x1);

    // ---- CSR build (shared by both layers) + input gather
    init_kernel<<<(N_NODES + 256) / 256, 256>>>();
    sumw_kernel<<<(N_EDGES + 255) / 256, 256>>>(ew);
    hist_kernel<<<(N_EDGES + 255) / 256, 256>>>(ei);
    scan_kernel<<<1, 1024>>>();
    scatter_kernel<<<(M_TOT + 255) / 256, 256>>>(ei, ew);
    gather_kernel<<<(N_NODES * 32 + 255) / 256, 256>>>(node_ids, emb);

    dim3 gb(32, 8);
    const int GB = (N_NODES + 63) / 64;          // 782
    const int AB = (N_NODES + 7) / 8;            // 6250 (8 warps/block)

    // ---- layer 1
    gemm_kernel<<<GB, gb>>>(x0, w1l, b1l, xl);
    gemm_kernel<<<GB, gb>>>(x0, w1r, b1r, xr);
    attn_kernel<<<AB, 256>>>(xl, xr, w1e, at1, bi1, g1, be1, x0, x1);

    // ---- layer 2
    gemm_kernel<<<GB, gb>>>(x1, w2l, b2l, xl);
    gemm_kernel<<<GB, gb>>>(x1, w2r, b2r, xr);
    attn_kernel<<<AB, 256>>>(xl, xr, w2e, at2, bi2, g2, be2, x1, out);
}

// round 2
// speedup vs baseline: 1.2101x; 1.2101x over previous
#include <cuda_runtime.h>
#include <math_constants.h>

#define N_NODES 50000
#define N_EDGES 800000
#define M_TOT   850000   // edges + self loops
#define D 128

#define SCAN_CHUNK 1024
#define SCAN_NBLK  ((N_NODES + SCAN_CHUNK - 1) / SCAN_CHUNK)   // 49

typedef unsigned long long u64;

// ---------------- scratch (device globals; no allocation allowed) ----------
__device__ float  g_sum[1];
__device__ int    g_deg[N_NODES + 1];
__device__ int    g_rowptr[N_NODES + 1];
__device__ int    g_cnt[N_NODES];
__device__ int    g_blk[SCAN_NBLK];
__device__ int    g_csr_src[M_TOT];
__device__ float  g_csr_w[M_TOT];
__device__ float4 g_x0[N_NODES * 32];
__device__ float4 g_xl[N_NODES * 32];
__device__ float4 g_xr[N_NODES * 32];
__device__ float4 g_x1[N_NODES * 32];

// ---------------- f32x2 helpers (FFMA2: PTX-only on sm_103a) ---------------
__device__ __forceinline__ u64 pk2(float a, float b) {
    u64 r; asm("mov.b64 %0,{%1,%2};" : "=l"(r) : "f"(a), "f"(b)); return r;
}
__device__ __forceinline__ void upk2(u64 v, float& a, float& b) {
    asm("mov.b64 {%0,%1},%2;" : "=f"(a), "=f"(b) : "l"(v));
}
__device__ __forceinline__ u64 ffma2(u64 a, u64 b, u64 c) {
    u64 d; asm("fma.rn.f32x2 %0,%1,%2,%3;" : "=l"(d) : "l"(a), "l"(b), "l"(c)); return d;
}

// ---------------- setup kernels --------------------------------------------
__global__ void init_kernel() {
    int i = blockIdx.x * blockDim.x + threadIdx.x;
    if (i <= N_NODES) g_deg[i] = (i < N_NODES) ? 1 : 0;   // +1 = self loop
    if (i == 0) g_sum[0] = 0.f;
}

// fused: histogram of dst + sum of edge weights
__global__ void hist_sumw_kernel(const int* __restrict__ ei, const float* __restrict__ ew) {
    int i = blockIdx.x * blockDim.x + threadIdx.x;
    float v = 0.f;
    if (i < N_EDGES) {
        atomicAdd(&g_deg[ei[N_EDGES + i]], 1);
        v = ew[i];
    }
    #pragma unroll
    for (int o = 16; o; o >>= 1) v += __shfl_xor_sync(0xffffffffu, v, o);
    if ((threadIdx.x & 31) == 0) atomicAdd(g_sum, v);
}

// ---- parallel scan, phase 1: per-block (1024-elem chunk) sums -------------
__global__ void scan_part_kernel() {
    __shared__ int ws[8];
    int b = blockIdx.x, tid = threadIdx.x;
    int base = b * SCAN_CHUNK + tid * 4;
    int s = 0;
    #pragma unroll
    for (int j = 0; j < 4; j++) {
        int idx = base + j;
        if (idx < N_NODES) s += g_deg[idx];
    }
    #pragma unroll
    for (int o = 16; o; o >>= 1) s += __shfl_xor_sync(0xffffffffu, s, o);
    if ((tid & 31) == 0) ws[tid >> 5] = s;
    __syncthreads();
    if (tid < 8) {
        int v = ws[tid];
        #pragma unroll
        for (int o = 4; o; o >>= 1) v += __shfl_xor_sync(0xffu, v, o);
        if (tid == 0) g_blk[b] = v;
    }
}

// ---- phase 2: exclusive scan of the 49 block sums (1 warp) ----------------
__global__ void scan_blk_kernel() {
    int lane = threadIdx.x;
    int v0 = (lane < SCAN_NBLK) ? g_blk[lane] : 0;
    int v1 = (lane + 32 < SCAN_NBLK) ? g_blk[lane + 32] : 0;
    int x = v0;
    #pragma unroll
    for (int o = 1; o < 32; o <<= 1) {
        int y = __shfl_up_sync(0xffffffffu, x, o);
        if (lane >= o) x += y;
    }
    int tot0 = __shfl_sync(0xffffffffu, x, 31);
    int z = v1;
    #pragma unroll
    for (int o = 1; o < 32; o <<= 1) {
        int y = __shfl_up_sync(0xffffffffu, z, o);
        if (lane >= o) z += y;
    }
    int tot1 = __shfl_sync(0xffffffffu, z, 31);
    if (lane < SCAN_NBLK)      g_blk[lane]      = x - v0;
    if (lane + 32 < SCAN_NBLK) g_blk[lane + 32] = tot0 + z - v1;
    if (lane == 0) g_rowptr[N_NODES] = tot0 + tot1;
}

// ---- phase 3: per-chunk exclusive scan + add block offset -----------------
__global__ void scan_final_kernel() {
    __shared__ int ws[8];
    int b = blockIdx.x, tid = threadIdx.x;
    int lane = tid & 31, wid = tid >> 5;
    int base = b * SCAN_CHUNK + tid * 4;
    int d0 = 0, d1 = 0, d2 = 0, d3 = 0;
    if (base + 0 < N_NODES) d0 = g_deg[base + 0];
    if (base + 1 < N_NODES) d1 = g_deg[base + 1];
    if (base + 2 < N_NODES) d2 = g_deg[base + 2];
    if (base + 3 < N_NODES) d3 = g_deg[base + 3];
    int tsum = d0 + d1 + d2 + d3;
    int x = tsum;
    #pragma unroll
    for (int o = 1; o < 32; o <<= 1) {
        int y = __shfl_up_sync(0xffffffffu, x, o);
        if (lane >= o) x += y;
    }
    if (lane == 31) ws[wid] = x;
    __syncthreads();
    if (tid < 8) {
        int w = ws[tid];
        #pragma unroll
        for (int o = 1; o < 8; o <<= 1) {
            int y = __shfl_up_sync(0xffu, w, o);
            if (tid >= o) w += y;
        }
        ws[tid] = w;
    }
    __syncthreads();
    int woff = (wid > 0) ? ws[wid - 1] : 0;
    int excl = g_blk[b] + woff + (x - tsum);
    int e0 = excl, e1 = e0 + d0, e2 = e1 + d1, e3 = e2 + d2;
    if (base + 0 < N_NODES) { g_rowptr[base + 0] = e0; g_cnt[base + 0] = e0; }
    if (base + 1 < N_NODES) { g_rowptr[base + 1] = e1; g_cnt[base + 1] = e1; }
    if (base + 2 < N_NODES) { g_rowptr[base + 2] = e2; g_cnt[base + 2] = e2; }
    if (base + 3 < N_NODES) { g_rowptr[base + 3] = e3; g_cnt[base + 3] = e3; }
}

__global__ void scatter_kernel(const int* __restrict__ ei, const float* __restrict__ ew) {
    int i = blockIdx.x * blockDim.x + threadIdx.x;
    if (i >= M_TOT) return;
    int s, d; float w;
    if (i < N_EDGES) { s = ei[i]; d = ei[N_EDGES + i]; w = ew[i]; }
    else             { s = d = i - N_EDGES; w = g_sum[0] * (1.0f / N_EDGES); }
    int pos = atomicAdd(&g_cnt[d], 1);
    g_csr_src[pos] = s;
    g_csr_w[pos]   = w;
}

__global__ void gather_kernel(const int* __restrict__ node_ids, const float* __restrict__ emb) {
    int i = blockIdx.x * blockDim.x + threadIdx.x;
    if (i >= N_NODES * 32) return;
    int node = i >> 5, c = i & 31;
    g_x0[i] = ((const float4*)emb)[node_ids[node] * 32 + c];
}

// ---------------- GEMM: Y[M,128] = X[M,128] @ W[128,128] + B ---------------
// block = (32,8): 64 rows x 128 cols per block. blockIdx.y picks (Wl,Bl,Yl)
// vs (Wr,Br,Yr) so both projections of a layer run in ONE launch (halves the
// tail-wave waste and launch count).
__global__ __launch_bounds__(256) void gemm2_kernel(
    const float* __restrict__ X,
    const float* __restrict__ Wl, const float* __restrict__ Bl, float* __restrict__ Yl,
    const float* __restrict__ Wr, const float* __restrict__ Br, float* __restrict__ Yr)
{
    const float* W = (blockIdx.y == 0) ? Wl : Wr;
    const float* B = (blockIdx.y == 0) ? Bl : Br;
    float*       Y = (blockIdx.y == 0) ? Yl : Yr;

    __shared__ float2 xs[32 * 128];           // [row_pair][k]
    const int tx = threadIdx.x, ty = threadIdx.y;
    const int t  = ty * 32 + tx;
    const int r0 = blockIdx.x * 64;

    #pragma unroll
    for (int i = 0; i < 4; i++) {
        int u  = t + 256 * i;                 // 0..1023
        int rp = u >> 5, c4 = u & 31;
        int ra = r0 + 2 * rp, rb = ra + 1;
        float4 a = (ra < N_NODES) ? *(const float4*)(X + ra * D + c4 * 4) : make_float4(0,0,0,0);
        float4 b = (rb < N_NODES) ? *(const float4*)(X + rb * D + c4 * 4) : make_float4(0,0,0,0);
        xs[rp * 128 + 4 * c4 + 0] = make_float2(a.x, b.x);
        xs[rp * 128 + 4 * c4 + 1] = make_float2(a.y, b.y);
        xs[rp * 128 + 4 * c4 + 2] = make_float2(a.z, b.z);
        xs[rp * 128 + 4 * c4 + 3] = make_float2(a.w, b.w);
    }
    __syncthreads();

    u64 acc[4][4];
    #pragma unroll
    for (int j = 0; j < 4; j++)
        #pragma unroll
        for (int c = 0; c < 4; c++) acc[j][c] = 0ull;

    const float4* W4 = (const float4*)W;
    #pragma unroll 4
    for (int k = 0; k < D; k += 2) {
        float4 wA = W4[k * 32 + tx];
        float4 wB = W4[(k + 1) * 32 + tx];
        u64 wA0 = pk2(wA.x, wA.x), wA1 = pk2(wA.y, wA.y);
        u64 wA2 = pk2(wA.z, wA.z), wA3 = pk2(wA.w, wA.w);
        u64 wB0 = pk2(wB.x, wB.x), wB1 = pk2(wB.y, wB.y);
        u64 wB2 = pk2(wB.z, wB.z), wB3 = pk2(wB.w, wB.w);
        #pragma unroll
        for (int j = 0; j < 4; j++) {
            float4 xv = *(const float4*)&xs[(ty * 4 + j) * 128 + k];
            u64 x0 = pk2(xv.x, xv.y);   // (row_e, row_o) at k
            u64 x1 = pk2(xv.z, xv.w);   // (row_e, row_o) at k+1
            acc[j][0] = ffma2(x0, wA0, acc[j][0]);
            acc[j][1] = ffma2(x0, wA1, acc[j][1]);
            acc[j][2] = ffma2(x0, wA2, acc[j][2]);
            acc[j][3] = ffma2(x0, wA3, acc[j][3]);
            acc[j][0] = ffma2(x1, wB0, acc[j][0]);
            acc[j][1] = ffma2(x1, wB1, acc[j][1]);
            acc[j][2] = ffma2(x1, wB2, acc[j][2]);
            acc[j][3] = ffma2(x1, wB3, acc[j][3]);
        }
    }

    float4 b4 = *(const float4*)(B + tx * 4);
    #pragma unroll
    for (int j = 0; j < 4; j++) {
        int rp = ty * 4 + j;
        int ra = r0 + 2 * rp, rb = ra + 1;
        float e0,o0,e1,o1,e2,o2,e3,o3;
        upk2(acc[j][0], e0, o0); upk2(acc[j][1], e1, o1);
        upk2(acc[j][2], e2, o2); upk2(acc[j][3], e3, o3);
        if (ra < N_NODES)
            *(float4*)(Y + ra * D + tx * 4) = make_float4(e0 + b4.x, e1 + b4.y, e2 + b4.z, e3 + b4.w);
        if (rb < N_NODES)
            *(float4*)(Y + rb * D + tx * 4) = make_float4(o0 + b4.x, o1 + b4.y, o2 + b4.z, o3 + b4.w);
    }
}

// ---------------- fused attention + aggregate + residual + LN --------------
// one warp per dst node; single pass with online softmax. The next edge's
// (src, w) AND its xl row are prefetched one iteration ahead so the L2
// gather latency overlaps the shfl reduction chain.
__global__ __launch_bounds__(256) void attn_kernel(
    const float* __restrict__ xl, const float* __restrict__ xr,
    const float* __restrict__ We, const float* __restrict__ att,
    const float* __restrict__ bias, const float* __restrict__ gam,
    const float* __restrict__ bet, const float* __restrict__ resid,
    float* __restrict__ out)
{
    int gw   = (blockIdx.x * blockDim.x + threadIdx.x) >> 5;
    int lane = threadIdx.x & 31;
    if (gw >= N_NODES) return;
    int c = lane * 4;

    float4 xr4 = *(const float4*)(xr + gw * D + c);
    float4 We4 = *(const float4*)(We + c);
    float4 at4 = *(const float4*)(att + c);

    int beg = g_rowptr[gw], end = g_rowptr[gw + 1];   // end > beg (self loop)
    float m = -CUDART_INF_F, s = 0.f;
    float ax = 0.f, ay = 0.f, az = 0.f, aw = 0.f;

    int   sn = g_csr_src[beg];
    float wc = g_csr_w[beg];
    float4 xv = *(const float4*)(xl + sn * D + c);

    for (int i = beg; i < end; i++) {
        // prefetch next edge (same address on final iter; harmless)
        int   ni  = (i + 1 < end) ? i + 1 : i;
        int   nsn = g_csr_src[ni];
        float nw  = g_csr_w[ni];
        float4 nxv = *(const float4*)(xl + nsn * D + c);

        float t0 = xv.x + xr4.x + wc * We4.x; t0 = fmaxf(t0, 0.2f * t0);
        float t1 = xv.y + xr4.y + wc * We4.y; t1 = fmaxf(t1, 0.2f * t1);
        float t2 = xv.z + xr4.z + wc * We4.z; t2 = fmaxf(t2, 0.2f * t2);
        float t3 = xv.w + xr4.w + wc * We4.w; t3 = fmaxf(t3, 0.2f * t3);
        float l = t0 * at4.x + t1 * at4.y + t2 * at4.z + t3 * at4.w;
        l += __shfl_xor_sync(0xffffffffu, l, 16);
        l += __shfl_xor_sync(0xffffffffu, l, 8);
        l += __shfl_xor_sync(0xffffffffu, l, 4);
        l += __shfl_xor_sync(0xffffffffu, l, 2);
        l += __shfl_xor_sync(0xffffffffu, l, 1);
        float nm = fmaxf(m, l);
        float cs = __expf(m - nm);   // 0 on first iter (m = -inf)
        float e  = __expf(l - nm);
        s  = s  * cs + e;
        ax = ax * cs + e * xv.x;
        ay = ay * cs + e * xv.y;
        az = az * cs + e * xv.z;
        aw = aw * cs + e * xv.w;
        m = nm;

        xv = nxv; wc = nw; sn = nsn;
    }

    float inv = 1.0f / s;
    float4 b4 = *(const float4*)(bias + c);
    float4 r4 = *(const float4*)(resid + gw * D + c);
    float hx = r4.x + ax * inv + b4.x;
    float hy = r4.y + ay * inv + b4.y;
    float hz = r4.z + az * inv + b4.z;
    float hw = r4.w + aw * inv + b4.w;

    float ps = hx + hy + hz + hw;
    ps += __shfl_xor_sync(0xffffffffu, ps, 16);
    ps += __shfl_xor_sync(0xffffffffu, ps, 8);
    ps += __shfl_xor_sync(0xffffffffu, ps, 4);
    ps += __shfl_xor_sync(0xffffffffu, ps, 2);
    ps += __shfl_xor_sync(0xffffffffu, ps, 1);
    float mu = ps * (1.0f / D);

    float dx = hx - mu, dy = hy - mu, dz = hz - mu, dw = hw - mu;
    float q = dx * dx + dy * dy + dz * dz + dw * dw;
    q += __shfl_xor_sync(0xffffffffu, q, 16);
    q += __shfl_xor_sync(0xffffffffu, q, 8);
    q += __shfl_xor_sync(0xffffffffu, q, 4);
    q += __shfl_xor_sync(0xffffffffu, q, 2);
    q += __shfl_xor_sync(0xffffffffu, q, 1);
    float var = q * (1.0f / D);
    float sc  = rsqrtf(var + 1e-5f);

    float4 g4  = *(const float4*)(gam + c);
    float4 be4 = *(const float4*)(bet + c);
    float4 o;
    o.x = dx * sc * g4.x + be4.x;
    o.y = dy * sc * g4.y + be4.y;
    o.z = dz * sc * g4.z + be4.z;
    o.w = dw * sc * g4.w + be4.w;
    *(float4*)(out + gw * D + c) = o;
}

// ---------------- host -----------------------------------------------------
extern "C" void kernel_launch(void* const* d_in, const int* in_sizes, int n_in,
                              void* d_out, int out_size)
{
    const int*   node_ids = (const int*)d_in[0];
    const int*   ei       = (const int*)d_in[1];
    const float* ew       = (const float*)d_in[2];
    const float* emb      = (const float*)d_in[3];
    const float* w1l = (const float*)d_in[4];
    const float* b1l = (const float*)d_in[5];
    const float* w1r = (const float*)d_in[6];
    const float* b1r = (const float*)d_in[7];
    const float* w1e = (const float*)d_in[8];
    const float* at1 = (const float*)d_in[9];
    const float* bi1 = (const float*)d_in[10];
    const float* g1  = (const float*)d_in[11];
    const float* be1 = (const float*)d_in[12];
    const float* w2l = (const float*)d_in[13];
    const float* b2l = (const float*)d_in[14];
    const float* w2r = (const float*)d_in[15];
    const float* b2r = (const float*)d_in[16];
    const float* w2e = (const float*)d_in[17];
    const float* at2 = (const float*)d_in[18];
    const float* bi2 = (const float*)d_in[19];
    const float* g2  = (const float*)d_in[20];
    const float* be2 = (const float*)d_in[21];
    float* out = (float*)d_out;

    float *x0, *xl, *xr, *x1;
    cudaGetSymbolAddress((void**)&x0, g_x0);
    cudaGetSymbolAddress((void**)&xl, g_xl);
    cudaGetSymbolAddress((void**)&xr, g_xr);
    cudaGetSymbolAddress((void**)&x1, g_x1);

    // ---- CSR build (shared by both layers) + input gather
    init_kernel<<<(N_NODES + 256) / 256, 256>>>();
    hist_sumw_kernel<<<(N_EDGES + 255) / 256, 256>>>(ei, ew);
    scan_part_kernel<<<SCAN_NBLK, 256>>>();
    scan_blk_kernel<<<1, 32>>>();
    scan_final_kernel<<<SCAN_NBLK, 256>>>();
    scatter_kernel<<<(M_TOT + 255) / 256, 256>>>(ei, ew);
    gather_kernel<<<(N_NODES * 32 + 255) / 256, 256>>>(node_ids, emb);

    dim3 gb(32, 8);
    dim3 gemm_grid((N_NODES + 63) / 64, 2);      // 782 x 2
    const int AB = (N_NODES + 7) / 8;            // 6250 (8 warps/block)

    // ---- layer 1
    gemm2_kernel<<<gemm_grid, gb>>>(x0, w1l, b1l, xl, w1r, b1r, xr);
    attn_kernel<<<AB, 256>>>(xl, xr, w1e, at1, bi1, g1, be1, x0, x1);

    // ---- layer 2
    gemm2_kernel<<<gemm_grid, gb>>>(x1, w2l, b2l, xl, w2r, b2r, xr);
    attn_kernel<<<AB, 256>>>(xl, xr, w2e, at2, bi2, g2, be2, x1, out);
}